// round 6
// baseline (speedup 1.0000x reference)
#include <cuda_runtime.h>
#include <cuda_bf16.h>
#include <math.h>
#include <stdint.h>

#define N_TOK   2048
#define D_MODEL 2048
#define KV_D    512

// ---------------- scratch ---------------------------------------------------
__device__ __nv_bfloat16 g_xh[N_TOK * D_MODEL];
__device__ __nv_bfloat16 g_xl[N_TOK * D_MODEL];
__device__ __nv_bfloat16 g_ch[N_TOK * D_MODEL];
__device__ __nv_bfloat16 g_cl[N_TOK * D_MODEL];
__device__ __nv_bfloat16 g_Qh[N_TOK * D_MODEL];
__device__ __nv_bfloat16 g_Ql[N_TOK * D_MODEL];
__device__ __nv_bfloat16 g_Kh[N_TOK * KV_D];
__device__ __nv_bfloat16 g_Kl[N_TOK * KV_D];
__device__ __nv_bfloat16 g_Vth[KV_D * N_TOK];   // [kv][d][n]
__device__ __nv_bfloat16 g_Vtl[KV_D * N_TOK];
__device__ __nv_bfloat16 g_WqTh[D_MODEL * D_MODEL];
__device__ __nv_bfloat16 g_WqTl[D_MODEL * D_MODEL];
__device__ __nv_bfloat16 g_WkTh[KV_D * D_MODEL];
__device__ __nv_bfloat16 g_WkTl[KV_D * D_MODEL];
__device__ __nv_bfloat16 g_WvTh[KV_D * D_MODEL];
__device__ __nv_bfloat16 g_WvTl[KV_D * D_MODEL];
__device__ __nv_bfloat16 g_WoTh[D_MODEL * D_MODEL];
__device__ __nv_bfloat16 g_WoTl[D_MODEL * D_MODEL];
__device__ float2 g_rope[N_TOK * 64];

__device__ __forceinline__ uint32_t smem_u32(const void* p) {
    uint32_t a;
    asm("{ .reg .u64 t; cvta.to.shared.u64 t, %1; cvt.u32.u64 %0, t; }"
        : "=r"(a) : "l"(p));
    return a;
}

#define LDSM4(r, addr)                                                        \
    asm volatile("ldmatrix.sync.aligned.m8n8.x4.shared.b16 {%0,%1,%2,%3}, [%4];" \
                 : "=r"((r)[0]), "=r"((r)[1]), "=r"((r)[2]), "=r"((r)[3])     \
                 : "r"(addr))

#define MMA16816(d, a, b0, b1)                                                \
    asm volatile("mma.sync.aligned.m16n8k16.row.col.f32.bf16.bf16.f32 "       \
                 "{%0,%1,%2,%3}, {%4,%5,%6,%7}, {%8,%9}, {%0,%1,%2,%3};"      \
                 : "+f"((d)[0]), "+f"((d)[1]), "+f"((d)[2]), "+f"((d)[3])     \
                 : "r"((a)[0]), "r"((a)[1]), "r"((a)[2]), "r"((a)[3]),        \
                   "r"(b0), "r"(b1))

__device__ __forceinline__ void cpa16(uint32_t dst, const void* src) {
    asm volatile("cp.async.cg.shared.global [%0], [%1], 16;" :: "r"(dst), "l"(src));
}
#define CPA_COMMIT asm volatile("cp.async.commit_group;" ::: "memory")
#define CPA_WAIT(n) asm volatile("cp.async.wait_group %0;" :: "n"(n) : "memory")

__device__ __forceinline__ float fexp(float x) {
    float t = x * 1.4426950408889634f;
    t = fmaxf(t, -126.0f);
    float n = floorf(t);
    float f = t - n;
    float p = 1.5403530393283621e-4f;
    p = fmaf(p, f, 1.3333558146428443e-3f);
    p = fmaf(p, f, 9.6181291076284772e-3f);
    p = fmaf(p, f, 5.5504108664821580e-2f);
    p = fmaf(p, f, 2.4022650695910071e-1f);
    p = fmaf(p, f, 6.9314718055994531e-1f);
    p = fmaf(p, f, 1.0f);
    return __int_as_float(((int)n + 127) << 23) * p;
}

__device__ __forceinline__ void split2(float a, float b, __nv_bfloat162& h,
                                       __nv_bfloat162& l) {
    __nv_bfloat16 ha = __float2bfloat16(a), hb = __float2bfloat16(b);
    h = __nv_bfloat162(ha, hb);
    l = __nv_bfloat162(__float2bfloat16(a - __bfloat162float(ha)),
                       __float2bfloat16(b - __bfloat162float(hb)));
}

// ---------------------------------------------------------------------------
// Prep mega-kernel: act split | 4 weight transposes | rope table.
// ---------------------------------------------------------------------------
__global__ void __launch_bounds__(256) prep_all(
    const float* __restrict__ x, const float* __restrict__ Wq,
    const float* __restrict__ Wk, const float* __restrict__ Wv,
    const float* __restrict__ Wo,
    __nv_bfloat16* __restrict__ xh, __nv_bfloat16* __restrict__ xl,
    __nv_bfloat16* __restrict__ qth, __nv_bfloat16* __restrict__ qtl,
    __nv_bfloat16* __restrict__ kth, __nv_bfloat16* __restrict__ ktl,
    __nv_bfloat16* __restrict__ vth, __nv_bfloat16* __restrict__ vtl,
    __nv_bfloat16* __restrict__ oth, __nv_bfloat16* __restrict__ otl,
    float2* __restrict__ tab) {
    const int bid = blockIdx.x;
    const int tid = threadIdx.x;
    if (bid < 4096) {
        int i = (bid * 256 + tid) * 4;
        float4 v = *(const float4*)(x + i);
        __nv_bfloat162 h0, l0, h1, l1;
        split2(v.x, v.y, h0, l0);
        split2(v.z, v.w, h1, l1);
        __nv_bfloat162* ph = (__nv_bfloat162*)(xh + i);
        __nv_bfloat162* pl = (__nv_bfloat162*)(xl + i);
        ph[0] = h0; ph[1] = h1;
        pl[0] = l0; pl[1] = l1;
    } else if (bid < 14336) {
        __shared__ float t[32][33];
        int wb = bid - 4096;
        const float* in; __nv_bfloat16 *doh, *dol; int Ndim, nx, sid;
        if (wb < 4096)      { in = Wq; doh = qth; dol = qtl; Ndim = D_MODEL; nx = 64; sid = wb; }
        else if (wb < 5120) { in = Wk; doh = kth; dol = ktl; Ndim = KV_D;   nx = 16; sid = wb - 4096; }
        else if (wb < 6144) { in = Wv; doh = vth; dol = vtl; Ndim = KV_D;   nx = 16; sid = wb - 5120; }
        else                { in = Wo; doh = oth; dol = otl; Ndim = D_MODEL; nx = 64; sid = wb - 6144; }
        int n0 = (sid % nx) * 32, k0 = (sid / nx) * 32;
        int tx = tid & 31, ty = tid >> 5;
#pragma unroll
        for (int i = 0; i < 4; ++i)
            t[ty + 8 * i][tx] = in[(size_t)(k0 + ty + 8 * i) * Ndim + n0 + tx];
        __syncthreads();
#pragma unroll
        for (int i = 0; i < 4; ++i) {
            int nl = ty + 8 * i;
            float v = t[tx][nl];
            __nv_bfloat16 h = __float2bfloat16(v);
            size_t o = (size_t)(n0 + nl) * D_MODEL + k0 + tx;
            doh[o] = h;
            dol[o] = __float2bfloat16(v - __bfloat162float(h));
        }
    } else {
        int idx = (bid - 14336) * 256 + tid;
        int t = idx >> 6, i = idx & 63;
        double inv = exp(-9.210340371976184 * ((double)i / 64.0));
        double ang = (double)t * inv;
        double k = floor(ang * 0.15915494309189535);
        float r = (float)(ang - k * 6.283185307179586);
        float s, c;
        sincosf(r, &s, &c);
        tab[idx] = make_float2(c, s);
    }
}

// ---------------------------------------------------------------------------
// cp.async 3-stage bf16x3 GEMM core. BM=BN=128, BK=32. 256 threads.
// smem: 3 stages x (Ah|Al|Bh|Bl) tiles, 80B row stride. 122880 B total.
// ---------------------------------------------------------------------------
#define GRS   80
#define GTB   (128 * GRS)       // 10240 per tile
#define GSBUF (4 * GTB)         // 40960 per stage
#define GSMEM (3 * GSBUF)       // 122880

__device__ __forceinline__ void gemm_issue(
    uint32_t sbase, int slot, int c, int K, int tid,
    const __nv_bfloat16* pAh, const __nv_bfloat16* pAl,
    const __nv_bfloat16* pBh, const __nv_bfloat16* pBl) {
    const __nv_bfloat16* bases[4] = {pAh, pAl, pBh, pBl};
    uint32_t stage = sbase + slot * GSBUF;
#pragma unroll
    for (int t = 0; t < 4; ++t) {
#pragma unroll
        for (int i = 0; i < 2; ++i) {
            int idx = tid + i * 256;
            int r = idx >> 2, cc = idx & 3;
            cpa16(stage + t * GTB + r * GRS + cc * 16,
                  (const char*)bases[t] + ((size_t)r * K + c * 32) * 2 + cc * 16);
        }
    }
}

__device__ __forceinline__ void gemm_core_async(
    const __nv_bfloat16* __restrict__ pAh, const __nv_bfloat16* __restrict__ pAl,
    const __nv_bfloat16* __restrict__ pBh, const __nv_bfloat16* __restrict__ pBl,
    int K, uint32_t sbase, float acc[2][8][4]) {
    const int tid = threadIdx.x;
    const int lane = tid & 31;
    const int wid = tid >> 5;
    const int warp_m = wid & 3;
    const int warp_n = wid >> 2;
    const int q = lane >> 3;
    const int rowA = (lane & 7) + (q & 1) * 8;
    const int colA = (q >> 1) * 16;
    const int rowB = (lane & 7) + (q >> 1) * 8;
    const int colB = (q & 1) * 16;

    const int NC = K / 32;
    gemm_issue(sbase, 0, 0, K, tid, pAh, pAl, pBh, pBl);
    CPA_COMMIT;
    gemm_issue(sbase, 1, 1, K, tid, pAh, pAl, pBh, pBl);
    CPA_COMMIT;

    int slot = 0;
    for (int c = 0; c < NC; ++c) {
        CPA_WAIT(1);
        __syncthreads();
        if (c + 2 < NC) {
            int ns = slot + 2;
            if (ns >= 3) ns -= 3;
            gemm_issue(sbase, ns, c + 2, K, tid, pAh, pAl, pBh, pBl);
        }
        CPA_COMMIT;

        const uint32_t sb = sbase + slot * GSBUF;
#pragma unroll
        for (int ks = 0; ks < 2; ++ks) {
            uint32_t ah[2][4], al[2][4], bh[4][4], bl[4][4];
#pragma unroll
            for (int im = 0; im < 2; ++im) {
                uint32_t ra = sb + (warp_m * 32 + im * 16 + rowA) * GRS + ks * 32 + colA;
                LDSM4(ah[im], ra);
                LDSM4(al[im], ra + GTB);
            }
#pragma unroll
            for (int ib = 0; ib < 4; ++ib) {
                uint32_t rb = sb + 2 * GTB + (warp_n * 64 + ib * 16 + rowB) * GRS + ks * 32 + colB;
                LDSM4(bh[ib], rb);
                LDSM4(bl[ib], rb + GTB);
            }
#pragma unroll
            for (int im = 0; im < 2; ++im)
#pragma unroll
                for (int j = 0; j < 8; ++j) {
                    const int f = j >> 1, h = (j & 1) * 2;
                    MMA16816(acc[im][j], ah[im], bh[f][h], bh[f][h + 1]);
                    MMA16816(acc[im][j], ah[im], bl[f][h], bl[f][h + 1]);
                    MMA16816(acc[im][j], al[im], bh[f][h], bh[f][h + 1]);
                }
        }
        if (++slot == 3) slot = 0;
    }
}

__device__ __forceinline__ void rope_split_store(
    const float2* __restrict__ tab, float v0, float v1, int row, int col, int N,
    __nv_bfloat16* __restrict__ oh, __nv_bfloat16* __restrict__ ol) {
    float2 cs = tab[row * 64 + ((col & 127) >> 1)];
    float oe = v0 * cs.x - v1 * cs.y;
    float oo = v0 * cs.y + v1 * cs.x;
    __nv_bfloat162 h, l;
    split2(oe, oo, h, l);
    *(__nv_bfloat162*)(oh + (size_t)row * N + col) = h;
    *(__nv_bfloat162*)(ol + (size_t)row * N + col) = l;
}

// ---- fused Q+K+V projection (384 blocks) ----------------------------------
__global__ void __launch_bounds__(256) hgemm_qkv(
    const __nv_bfloat16* __restrict__ Ah, const __nv_bfloat16* __restrict__ Al,
    const __nv_bfloat16* __restrict__ QBh, const __nv_bfloat16* __restrict__ QBl,
    const __nv_bfloat16* __restrict__ KBh, const __nv_bfloat16* __restrict__ KBl,
    const __nv_bfloat16* __restrict__ VBh, const __nv_bfloat16* __restrict__ VBl,
    __nv_bfloat16* __restrict__ qh, __nv_bfloat16* __restrict__ ql,
    __nv_bfloat16* __restrict__ kh, __nv_bfloat16* __restrict__ kl,
    __nv_bfloat16* __restrict__ vth, __nv_bfloat16* __restrict__ vtl,
    const float2* __restrict__ tab) {
    extern __shared__ char smem[];
    const uint32_t sbase = smem_u32(smem);
    const int bid = blockIdx.x;
    const int K = D_MODEL;
    int kind, m0, n0;
    const __nv_bfloat16 *Bh, *Bl;
    if (bid < 256)      { kind = 0; m0 = (bid >> 4) * 128; n0 = (bid & 15) * 128; Bh = QBh; Bl = QBl; }
    else if (bid < 320) { int s = bid - 256; kind = 1; m0 = (s >> 2) * 128; n0 = (s & 3) * 128; Bh = KBh; Bl = KBl; }
    else                { int s = bid - 320; kind = 2; m0 = (s >> 2) * 128; n0 = (s & 3) * 128; Bh = VBh; Bl = VBl; }

    float acc[2][8][4];
#pragma unroll
    for (int im = 0; im < 2; ++im)
#pragma unroll
        for (int j = 0; j < 8; ++j)
#pragma unroll
            for (int e = 0; e < 4; ++e) acc[im][j][e] = 0.f;
    gemm_core_async(Ah + (size_t)m0 * K, Al + (size_t)m0 * K,
                    Bh + (size_t)n0 * K, Bl + (size_t)n0 * K, K, sbase, acc);

    const int tid = threadIdx.x;
    const int lane = tid & 31, wid = tid >> 5;
    const int q4 = lane >> 2, l4 = lane & 3;
    if (kind == 0 || kind == 1) {
        const int N = (kind == 0) ? D_MODEL : KV_D;
        __nv_bfloat16* oh = (kind == 0) ? qh : kh;
        __nv_bfloat16* ol = (kind == 0) ? ql : kl;
#pragma unroll
        for (int im = 0; im < 2; ++im)
#pragma unroll
            for (int j = 0; j < 8; ++j) {
                int row = m0 + (wid & 3) * 32 + im * 16 + q4;
                int col = n0 + (wid >> 2) * 64 + j * 8 + l4 * 2;
                rope_split_store(tab, acc[im][j][0], acc[im][j][1], row, col, N, oh, ol);
                rope_split_store(tab, acc[im][j][2], acc[im][j][3], row + 8, col, N, oh, ol);
            }
    } else {
        __syncthreads();
        float* tS = (float*)smem;  // [128 d][132]
#pragma unroll
        for (int im = 0; im < 2; ++im)
#pragma unroll
            for (int j = 0; j < 8; ++j) {
                int r = (wid & 3) * 32 + im * 16 + q4;
                int cl = (wid >> 2) * 64 + j * 8 + l4 * 2;
                tS[cl * 132 + r] = acc[im][j][0];
                tS[(cl + 1) * 132 + r] = acc[im][j][1];
                tS[cl * 132 + r + 8] = acc[im][j][2];
                tS[(cl + 1) * 132 + r + 8] = acc[im][j][3];
            }
        __syncthreads();
        const int dkv = n0 >> 7;
        const int d = tid >> 1, half = (tid & 1) * 64;
        size_t dst = (size_t)dkv * 128 * N_TOK + (size_t)d * N_TOK + m0 + half;
#pragma unroll
        for (int k = 0; k < 64; k += 2) {
            __nv_bfloat162 h, l;
            split2(tS[d * 132 + half + k], tS[d * 132 + half + k + 1], h, l);
            *(__nv_bfloat162*)(vth + dst + k) = h;
            *(__nv_bfloat162*)(vtl + dst + k) = l;
        }
    }
}

// ---- output projection ----------------------------------------------------
__global__ void __launch_bounds__(256) hgemm_o(
    const __nv_bfloat16* __restrict__ Ah, const __nv_bfloat16* __restrict__ Al,
    const __nv_bfloat16* __restrict__ Bh, const __nv_bfloat16* __restrict__ Bl,
    float* __restrict__ C) {
    extern __shared__ char smem[];
    const uint32_t sbase = smem_u32(smem);
    const int m0 = blockIdx.y * 128, n0 = blockIdx.x * 128;
    const int K = D_MODEL, N = D_MODEL;
    float acc[2][8][4];
#pragma unroll
    for (int im = 0; im < 2; ++im)
#pragma unroll
        for (int j = 0; j < 8; ++j)
#pragma unroll
            for (int e = 0; e < 4; ++e) acc[im][j][e] = 0.f;
    gemm_core_async(Ah + (size_t)m0 * K, Al + (size_t)m0 * K,
                    Bh + (size_t)n0 * K, Bl + (size_t)n0 * K, K, sbase, acc);
    const int lane = threadIdx.x & 31, wid = threadIdx.x >> 5;
#pragma unroll
    for (int im = 0; im < 2; ++im)
#pragma unroll
        for (int j = 0; j < 8; ++j) {
            int row = m0 + (wid & 3) * 32 + im * 16 + (lane >> 2);
            int col = n0 + (wid >> 2) * 64 + j * 8 + (lane & 3) * 2;
            *(float2*)(C + (size_t)row * N + col) = make_float2(acc[im][j][0], acc[im][j][1]);
            *(float2*)(C + (size_t)(row + 8) * N + col) = make_float2(acc[im][j][2], acc[im][j][3]);
        }
}

// ---------------------------------------------------------------------------
// Flash attention: Q resident, K double-buffered cp.async, V pipelined.
// ---------------------------------------------------------------------------
#define RSQ 272
#define RSV 144
#define OQH 0
#define OQL 34816
#define OKST 69632            // + s*34816 ; Kh at +0, Kl at +17408
#define OVH 139264
#define OVL 157696
#define OPH 176128
#define OPL 194560
#define FSMEM 212992

__global__ void __launch_bounds__(256, 1) flash_mma(
    const __nv_bfloat16* __restrict__ Qh, const __nv_bfloat16* __restrict__ Ql,
    const __nv_bfloat16* __restrict__ Kh, const __nv_bfloat16* __restrict__ Kl,
    const __nv_bfloat16* __restrict__ Vth, const __nv_bfloat16* __restrict__ Vtl,
    __nv_bfloat16* __restrict__ ch, __nv_bfloat16* __restrict__ cl) {
    const int qt = gridDim.x - 1 - blockIdx.x;
    const int h  = blockIdx.y;
    const int g  = h >> 2, kv = h & 3;
    const int qcol0 = g * 512 + kv * 128;
    const int kcol0 = kv * 128;
    const int ocol0 = (kv * 4 + g) * 128;
    const __nv_bfloat16* vh = Vth + (size_t)kv * 128 * N_TOK;
    const __nv_bfloat16* vl = Vtl + (size_t)kv * 128 * N_TOK;

    extern __shared__ char smem[];
    const uint32_t sbase = smem_u32(smem);

    const int tid = threadIdx.x;
    const int lane = tid & 31;
    const int warp_m = tid >> 5;
    const int q4 = lane >> 2, l4 = lane & 3;
    const int qq = lane >> 3;
    const int rowA = (lane & 7) + (qq & 1) * 8;
    const int colA = (qq >> 1) * 16;
    const int rowB = (lane & 7) + (qq >> 1) * 8;
    const int colB = (qq & 1) * 16;
    const float SCALE = 0.08838834764831845f;

    // Q tile -> smem (visible after first in-loop sync)
#pragma unroll
    for (int i = 0; i < 8; ++i) {
        int idx = tid + i * 256;
        int r = idx >> 4, c = idx & 15;
        size_t go = (size_t)(qt * 128 + r) * D_MODEL + qcol0 + c * 8;
        *(uint4*)(smem + OQH + r * RSQ + c * 16) = *(const uint4*)(Qh + go);
        *(uint4*)(smem + OQL + r * RSQ + c * 16) = *(const uint4*)(Ql + go);
    }

    // issue K(0) into stage 0 (group 0)
    {
#pragma unroll
        for (int i = 0; i < 8; ++i) {
            int idx = tid + i * 256;
            int half = i >> 2;                       // 0: Kh, 1: Kl
            int li = idx & 1023;
            int r = li >> 4, c = li & 15;
            const __nv_bfloat16* src = half ? Kl : Kh;
            cpa16(sbase + OKST + half * 17408 + r * RSQ + c * 16,
                  src + (size_t)r * KV_D + kcol0 + c * 8);
        }
        CPA_COMMIT;
    }

    float o[16][4];
#pragma unroll
    for (int f = 0; f < 16; ++f)
#pragma unroll
        for (int e = 0; e < 4; ++e) o[f][e] = 0.f;
    float m0 = -1e30f, m1 = -1e30f, l0 = 0.f, l1 = 0.f;

    const int nkt = 2 * qt + 2;
    for (int kt = 0; kt < nkt; ++kt) {
        __syncthreads();   // all warps done reading V(kt-1), P(kt-1), K(kt-1)

        // issue V(kt) and K(kt+1) (group kt+1)
#pragma unroll
        for (int i = 0; i < 8; ++i) {
            int idx = tid + i * 256;
            int half = i >> 2;
            int li = idx & 1023;
            int r = li >> 3, c = li & 7;
            const __nv_bfloat16* src = half ? vl : vh;
            cpa16(sbase + (half ? OVL : OVH) + r * RSV + c * 16,
                  src + (size_t)r * N_TOK + kt * 64 + c * 8);
        }
        if (kt + 1 < nkt) {
            uint32_t kst = sbase + OKST + ((kt + 1) & 1) * 34816;
#pragma unroll
            for (int i = 0; i < 8; ++i) {
                int idx = tid + i * 256;
                int half = i >> 2;
                int li = idx & 1023;
                int r = li >> 4, c = li & 15;
                const __nv_bfloat16* src = half ? Kl : Kh;
                cpa16(kst + half * 17408 + r * RSQ + c * 16,
                      src + (size_t)((kt + 1) * 64 + r) * KV_D + kcol0 + c * 8);
            }
        }
        CPA_COMMIT;

        CPA_WAIT(1);        // K(kt) complete
        __syncthreads();

        const int rbase = qt * 128 + warp_m * 16;
        const bool active = (kt * 64) <= (rbase + 15);
        const uint32_t kst = sbase + OKST + (kt & 1) * 34816;

        if (active) {
            float sacc[8][4];
#pragma unroll
            for (int j = 0; j < 8; ++j)
#pragma unroll
                for (int e = 0; e < 4; ++e) sacc[j][e] = 0.f;
#pragma unroll
            for (int ks = 0; ks < 8; ++ks) {
                uint32_t ah[4], al[4], bh[4], bl[4];
                uint32_t ra = sbase + OQH + (warp_m * 16 + rowA) * RSQ + ks * 32 + colA;
                LDSM4(ah, ra);
                LDSM4(al, ra + (OQL - OQH));
#pragma unroll
                for (int ib = 0; ib < 4; ++ib) {
                    uint32_t rb = kst + (ib * 16 + rowB) * RSQ + ks * 32 + colB;
                    LDSM4(bh, rb);
                    LDSM4(bl, rb + 17408);
#pragma unroll
                    for (int half = 0; half < 2; ++half) {
                        MMA16816(sacc[ib * 2 + half], ah, bh[half * 2], bh[half * 2 + 1]);
                        MMA16816(sacc[ib * 2 + half], ah, bl[half * 2], bl[half * 2 + 1]);
                        MMA16816(sacc[ib * 2 + half], al, bh[half * 2], bh[half * 2 + 1]);
                    }
                }
            }
            const bool needMask = (kt * 64 + 63) > rbase;
#pragma unroll
            for (int j = 0; j < 8; ++j)
#pragma unroll
                for (int e = 0; e < 4; ++e) {
                    float v = sacc[j][e] * SCALE;
                    if (needMask) {
                        int rg = rbase + q4 + (e >> 1) * 8;
                        int kg = kt * 64 + j * 8 + l4 * 2 + (e & 1);
                        if (kg > rg) v = -1e30f;
                    }
                    sacc[j][e] = v;
                }
            float mx0 = -1e30f, mx1 = -1e30f;
#pragma unroll
            for (int j = 0; j < 8; ++j) {
                mx0 = fmaxf(mx0, fmaxf(sacc[j][0], sacc[j][1]));
                mx1 = fmaxf(mx1, fmaxf(sacc[j][2], sacc[j][3]));
            }
            mx0 = fmaxf(mx0, __shfl_xor_sync(0xffffffffu, mx0, 1));
            mx0 = fmaxf(mx0, __shfl_xor_sync(0xffffffffu, mx0, 2));
            mx1 = fmaxf(mx1, __shfl_xor_sync(0xffffffffu, mx1, 1));
            mx1 = fmaxf(mx1, __shfl_xor_sync(0xffffffffu, mx1, 2));
            float nm0 = fmaxf(m0, mx0), nm1 = fmaxf(m1, mx1);
            float corr0 = fexp(m0 - nm0), corr1 = fexp(m1 - nm1);
            m0 = nm0; m1 = nm1;
            float s0 = 0.f, s1 = 0.f;
            uint32_t prow0 = sbase + OPH + (warp_m * 16 + q4) * RSV + l4 * 4;
            uint32_t prow1 = prow0 + 8 * RSV;
#pragma unroll
            for (int j = 0; j < 8; ++j) {
                float p00 = fexp(sacc[j][0] - m0);
                float p01 = fexp(sacc[j][1] - m0);
                float p10 = fexp(sacc[j][2] - m1);
                float p11 = fexp(sacc[j][3] - m1);
                s0 += p00 + p01; s1 += p10 + p11;
                __nv_bfloat162 hp0, lp0, hp1, lp1;
                split2(p00, p01, hp0, lp0);
                split2(p10, p11, hp1, lp1);
                asm volatile("st.shared.b32 [%0], %1;" :: "r"(prow0 + j * 16), "r"(*(uint32_t*)&hp0));
                asm volatile("st.shared.b32 [%0], %1;" :: "r"(prow1 + j * 16), "r"(*(uint32_t*)&hp1));
                asm volatile("st.shared.b32 [%0], %1;" :: "r"(prow0 + (OPL - OPH) + j * 16), "r"(*(uint32_t*)&lp0));
                asm volatile("st.shared.b32 [%0], %1;" :: "r"(prow1 + (OPL - OPH) + j * 16), "r"(*(uint32_t*)&lp1));
            }
            s0 += __shfl_xor_sync(0xffffffffu, s0, 1);
            s0 += __shfl_xor_sync(0xffffffffu, s0, 2);
            s1 += __shfl_xor_sync(0xffffffffu, s1, 1);
            s1 += __shfl_xor_sync(0xffffffffu, s1, 2);
            l0 = l0 * corr0 + s0;
            l1 = l1 * corr1 + s1;
#pragma unroll
            for (int f = 0; f < 16; ++f) {
                o[f][0] *= corr0; o[f][1] *= corr0;
                o[f][2] *= corr1; o[f][3] *= corr1;
            }
        }

        CPA_WAIT(0);        // V(kt) complete (K(kt+1) also done by now)
        __syncthreads();    // P + V visible

        if (active) {
#pragma unroll
            for (int ks = 0; ks < 4; ++ks) {
                uint32_t pa[4], pl_[4];
                uint32_t raddr = sbase + OPH + (warp_m * 16 + rowA) * RSV + ks * 32 + colA;
                LDSM4(pa, raddr);
                LDSM4(pl_, raddr + (OPL - OPH));
#pragma unroll
                for (int ib = 0; ib < 8; ++ib) {
                    uint32_t vb[4], vbl[4];
                    uint32_t b0 = sbase + OVH + (ib * 16 + rowB) * RSV + ks * 32 + colB;
                    LDSM4(vb, b0);
                    LDSM4(vbl, b0 + (OVL - OVH));
#pragma unroll
                    for (int half = 0; half < 2; ++half) {
                        MMA16816(o[ib * 2 + half], pa, vb[half * 2], vb[half * 2 + 1]);
                        MMA16816(o[ib * 2 + half], pa, vbl[half * 2], vbl[half * 2 + 1]);
                        MMA16816(o[ib * 2 + half], pl_, vb[half * 2], vb[half * 2 + 1]);
                    }
                }
            }
        }
    }

    float i0 = 1.f / l0, i1 = 1.f / l1;
    int row0 = qt * 128 + warp_m * 16 + q4;
#pragma unroll
    for (int f = 0; f < 16; ++f) {
        int col = ocol0 + f * 8 + l4 * 2;
        __nv_bfloat162 h0, l0v, h1, l1v;
        split2(o[f][0] * i0, o[f][1] * i0, h0, l0v);
        split2(o[f][2] * i1, o[f][3] * i1, h1, l1v);
        *(__nv_bfloat162*)(ch + (size_t)row0 * D_MODEL + col) = h0;
        *(__nv_bfloat162*)(ch + (size_t)(row0 + 8) * D_MODEL + col) = h1;
        *(__nv_bfloat162*)(cl + (size_t)row0 * D_MODEL + col) = l0v;
        *(__nv_bfloat162*)(cl + (size_t)(row0 + 8) * D_MODEL + col) = l1v;
    }
}

// ---------------------------------------------------------------------------
extern "C" void kernel_launch(void* const* d_in, const int* in_sizes, int n_in,
                              void* d_out, int out_size) {
    const float* x  = (const float*)d_in[0];
    const float* Wq = (const float*)d_in[1];
    const float* Wk = (const float*)d_in[2];
    const float* Wv = (const float*)d_in[3];
    const float* Wo = (const float*)d_in[4];
    float* out = (float*)d_out;

    __nv_bfloat16 *xh, *xl, *ch, *cl, *qh, *ql, *kh, *kl, *vth, *vtl;
    __nv_bfloat16 *qth, *qtl, *kth, *ktl, *vwh, *vwl, *oth, *otl;
    float2* tab;
    cudaGetSymbolAddress((void**)&xh, g_xh);   cudaGetSymbolAddress((void**)&xl, g_xl);
    cudaGetSymbolAddress((void**)&ch, g_ch);   cudaGetSymbolAddress((void**)&cl, g_cl);
    cudaGetSymbolAddress((void**)&qh, g_Qh);   cudaGetSymbolAddress((void**)&ql, g_Ql);
    cudaGetSymbolAddress((void**)&kh, g_Kh);   cudaGetSymbolAddress((void**)&kl, g_Kl);
    cudaGetSymbolAddress((void**)&vth, g_Vth); cudaGetSymbolAddress((void**)&vtl, g_Vtl);
    cudaGetSymbolAddress((void**)&qth, g_WqTh); cudaGetSymbolAddress((void**)&qtl, g_WqTl);
    cudaGetSymbolAddress((void**)&kth, g_WkTh); cudaGetSymbolAddress((void**)&ktl, g_WkTl);
    cudaGetSymbolAddress((void**)&vwh, g_WvTh); cudaGetSymbolAddress((void**)&vwl, g_WvTl);
    cudaGetSymbolAddress((void**)&oth, g_WoTh); cudaGetSymbolAddress((void**)&otl, g_WoTl);
    cudaGetSymbolAddress((void**)&tab, g_rope);

    cudaFuncSetAttribute(hgemm_qkv, cudaFuncAttributeMaxDynamicSharedMemorySize, GSMEM);
    cudaFuncSetAttribute(hgemm_o,   cudaFuncAttributeMaxDynamicSharedMemorySize, GSMEM);
    cudaFuncSetAttribute(flash_mma, cudaFuncAttributeMaxDynamicSharedMemorySize, FSMEM);

    // 1: prep (act split + weight transposes + rope table)
    prep_all<<<14848, 256>>>(x, Wq, Wk, Wv, Wo, xh, xl, qth, qtl, kth, ktl,
                             vwh, vwl, oth, otl, tab);
    // 2: fused Q/K/V projections (+rope, +V transpose)
    hgemm_qkv<<<384, 256, GSMEM>>>(xh, xl, qth, qtl, kth, ktl, vwh, vwl,
                                   qh, ql, kh, kl, vth, vtl, tab);
    // 3: attention
    flash_mma<<<dim3(N_TOK / 128, 16), 256, FSMEM>>>(qh, ql, kh, kl, vth, vtl, ch, cl);
    // 4: output projection
    hgemm_o<<<dim3(16, 16), 256, GSMEM>>>(ch, cl, oth, otl, out);

    (void)in_sizes; (void)n_in; (void)out_size;
}